// round 12
// baseline (speedup 1.0000x reference)
#include <cuda_runtime.h>
#include <cuda_fp16.h>
#include <stdint.h>

#define Bn 8
#define Hc 96
#define Wc 128
#define HW (Hc*Wc)

// ---------------- scratch (__device__ globals; allocation-free rule) -------
__device__ __half g_corr_h[(size_t)Bn*HW*384];
__device__ __half g_cor1_h[(size_t)Bn*HW*256];
__device__ __half g_flo1_h[(size_t)Bn*HW*128];
__device__ __half g_cat_h [(size_t)Bn*HW*256];
__device__ __half g_im7  [(size_t)Bn*HW*128];     // im2col of flow (7x7, Cin=2)
__device__ __half g_wc1_h[1*256*384];
__device__ __half g_wc2_h[9*256*256];
__device__ __half g_wf2_h[9*128*128];
__device__ __half g_wo_h [9*128*256];
__device__ __half g_wf1_h[128*128];               // im2col-matched 7x7 weights

// ---------------- helpers ---------------------------------------------------
__device__ __forceinline__ uint32_t s2u(const void* p) {
    uint32_t a;
    asm("{ .reg .u64 t; cvta.to.shared.u64 t, %1; cvt.u32.u64 %0, t; }"
        : "=r"(a) : "l"(p));
    return a;
}
#define SWZ(x) ((x) ^ (((x) >> 3) & 0x70))

__device__ __forceinline__ void ldsm4(uint32_t* r, uint32_t addr) {
    asm volatile("ldmatrix.sync.aligned.m8n8.x4.shared.b16 {%0,%1,%2,%3}, [%4];"
        : "=r"(r[0]), "=r"(r[1]), "=r"(r[2]), "=r"(r[3]) : "r"(addr));
}
__device__ __forceinline__ void mma16816(float* d, const uint32_t* a,
                                          uint32_t b0, uint32_t b1) {
    asm volatile(
        "mma.sync.aligned.m16n8k16.row.col.f32.f16.f16.f32 "
        "{%0,%1,%2,%3}, {%4,%5,%6,%7}, {%8,%9}, {%0,%1,%2,%3};"
        : "+f"(d[0]), "+f"(d[1]), "+f"(d[2]), "+f"(d[3])
        : "r"(a[0]), "r"(a[1]), "r"(a[2]), "r"(a[3]), "r"(b0), "r"(b1));
}
__device__ __forceinline__ void cpa16(uint32_t s, const void* g, bool p) {
    asm volatile("cp.async.ca.shared.global [%0], [%1], 16, %2;"
        :: "r"(s), "l"(g), "r"(p ? 16u : 0u));
}
__device__ __forceinline__ void cpa_commit() {
    asm volatile("cp.async.commit_group;" ::: "memory");
}
__device__ __forceinline__ void cpa_wait0() {
    asm volatile("cp.async.wait_group 0;" ::: "memory");
}

// ---------------- weight prep (ALL layers, one launch) ----------------------
__device__ __forceinline__ void prep1(const float* __restrict__ w, int cout,
                                      int cin, int taps, int coPad, int Cpad,
                                      __half* __restrict__ dst, size_t i)
{
    int ci = (int)(i % Cpad);
    size_t t = i / Cpad;
    int co = (int)(t % coPad);
    int tap = (int)(t / coPad);
    float v = 0.f;
    if (co < cout && ci < cin)
        v = w[((size_t)co * cin + ci) * taps + tap];
    dst[i] = __float2half(v);
}

__global__ void wprep_all_k(const float* __restrict__ wc1, const float* __restrict__ wc2,
                            const float* __restrict__ wf2, const float* __restrict__ wo,
                            const float* __restrict__ wf1,
                            __half* __restrict__ oc1, __half* __restrict__ oc2,
                            __half* __restrict__ of2, __half* __restrict__ oo,
                            __half* __restrict__ of1)
{
    const size_t n1 = 98304, n2 = 589824, n3 = 147456, n4 = 294912, n5 = 16384;
    const size_t total = n1 + n2 + n3 + n4 + n5;
    for (size_t i = (size_t)blockIdx.x * blockDim.x + threadIdx.x; i < total;
         i += (size_t)gridDim.x * blockDim.x) {
        if (i < n1)                     prep1(wc1, 256, 324, 1, 256, 384, oc1, i);
        else if (i < n1 + n2)           prep1(wc2, 192, 256, 9, 256, 256, oc2, i - n1);
        else if (i < n1 + n2 + n3)      prep1(wf2,  64, 128, 9, 128, 128, of2, i - n1 - n2);
        else if (i < n1 + n2 + n3 + n4) prep1(wo,  126, 256, 9, 128, 256, oo,  i - n1 - n2 - n3);
        else {
            size_t i5 = i - n1 - n2 - n3 - n4;
            int co = (int)(i5 >> 7), c = (int)(i5 & 127);
            float v = 0.f;
            if (c < 98)   // c = dyx*2 + ci ; w[co][ci][dyx]
                v = wf1[(size_t)co * 98 + (c & 1) * 49 + (c >> 1)];
            of1[i5] = __float2half(v);
        }
    }
}

// ---------------- corr NCHW fp32 -> NHWC fp16 (Cpad=384, zero pad) ----------
__global__ __launch_bounds__(256) void corr2nhwc_k(
    const float* __restrict__ corr, __half* __restrict__ oh)
{
    const int c0 = blockIdx.x * 32, h = blockIdx.y, b = blockIdx.z;
    __shared__ float t[32][129];
    for (int i = threadIdx.x; i < 32 * 128; i += 256) {
        int ci = i >> 7, px = i & 127;
        float v = 0.f;
        if (c0 + ci < 324)
            v = corr[((size_t)b * 324 + c0 + ci) * HW + h * Wc + px];
        t[ci][px] = v;
    }
    __syncthreads();
    for (int i = threadIdx.x; i < 32 * 128; i += 256) {
        int px = i >> 5, ci = i & 31;
        size_t o = (((size_t)b * Hc + h) * Wc + px) * 384 + c0 + ci;
        oh[o] = __float2half(t[ci][px]);
    }
}

// ---------------- im2col for the 7x7 conv: flow NCHW -> [B,H,W,128] fp16 ----
__global__ __launch_bounds__(128) void im2col7_k(
    const float* __restrict__ flow, __half* __restrict__ dst)
{
    const int w = threadIdx.x, h = blockIdx.x, b = blockIdx.y;
    __align__(16) __half v[128];
#pragma unroll
    for (int c = 98; c < 128; c++) v[c] = __float2half(0.f);
#pragma unroll
    for (int dy = 0; dy < 7; dy++) {
        int hh = h + dy - 3;
#pragma unroll
        for (int dx = 0; dx < 7; dx++) {
            int ww = w + dx - 3;
            bool p = ((unsigned)hh < Hc) && ((unsigned)ww < Wc);
#pragma unroll
            for (int ci = 0; ci < 2; ci++) {
                float f = p ? flow[((size_t)(b * 2 + ci) * Hc + hh) * Wc + ww] : 0.f;
                v[(dy * 7 + dx) * 2 + ci] = __float2half(f);
            }
        }
    }
    __half* o = dst + (((size_t)b * Hc + h) * Wc + w) * 128;
#pragma unroll
    for (int j = 0; j < 16; j++)
        reinterpret_cast<uint4*>(o)[j] = reinterpret_cast<uint4*>(v)[j];
}

// ---------------- HMMA conv-as-GEMM, 64co x 512px, 512 threads --------------
// Block: 512 thr / 16 warps; tile 64co x 512px (FOUR image rows h0..h0+3).
// Warp w: row r4=w>>2 (0..3); pq=w&3: px half pxb=(pq&1)*64, co stripe
// cs=(pq>>1)*32. Warp tile 32co x 64px -> d[16][4] = 64 accum regs.
// A: 2-slot ring (8KB each), staged per step (fully overlapped).
// B: (4 + kw - 1) row-tiles [130px][64ci], staged once per kc.
// smem: A 16384 @0 ; B <=6*16640 @16384 (total 116224). Epilogue reuses all.
#define SMEM_BYTES 116224

__global__ __launch_bounds__(512, 1) void conv_mma4_k(
    const __half* __restrict__ ah, int Cpad, int kcNum,
    const __half* __restrict__ wgh,
    int coPad, const float* __restrict__ bias, int coutUsed,
    int taps, int kw, int kr,
    __half* __restrict__ oh, int outCpad, int outCoff,
    float* __restrict__ of32)
{
    extern __shared__ __align__(16) char smem[];
    const uint32_t sA = s2u(smem);
    const uint32_t sB = sA + 16384u;

    const int tid = threadIdx.x;
    const int warp = tid >> 5, lane = tid & 31;
    const int mt = blockIdx.x, h0 = blockIdx.y * 4, b = blockIdx.z;
    const int r4 = warp >> 2;             // image row within block (0..3)
    const int pq = warp & 3;
    const int pxb = (pq & 1) * 64;        // px half
    const int cs  = (pq >> 1) * 32;       // co stripe
    const int gid = lane >> 2, tig = lane & 3;
    const int midx = lane >> 3, l7 = lane & 7;

    float d[16][4];
#pragma unroll
    for (int i = 0; i < 16; i++)
#pragma unroll
        for (int j = 0; j < 4; j++) d[i][j] = 0.f;

    const int nsteps = kcNum * taps;
    const int nTile = 4 + kw - 1;

    // stage A (64 co x 64 ci fp16) for step s into slot s&1
    auto stageA = [&](int s) {
        const int kcs = s / taps, tp = s % taps;
        const __half* src = wgh + (size_t)kcs * 64;
        const uint32_t d0 = sA + (uint32_t)(s & 1) * 8192u;
        int row = tid >> 3, c16 = tid & 7;   // 512 = 64 rows x 8 chunks
        cpa16(d0 + SWZ((uint32_t)(row * 128 + c16 * 16)),
              src + ((size_t)tp * coPad + mt * 64 + row) * Cpad + c16 * 8, true);
    };
    // stage all B row-tiles for chunk kc
    auto stageBall = [&](int kc) {
        const int tot = nTile * 1040;
        for (int i = tid; i < tot; i += 512) {
            int t = i / 1040, rem = i - t * 1040;
            int row = rem >> 3, c16 = rem & 7;
            int px = row - 1;
            int hh = h0 + t - kr;
            bool p = ((unsigned)px < Wc) && ((unsigned)hh < Hc);
            const __half* g = ah + (((size_t)b * Hc + hh) * Wc + px) * Cpad
                            + kc * 64 + c16 * 8;
            cpa16(sB + t * 16640 + SWZ(row * 128 + c16 * 16), p ? g : ah, p);
        }
    };

    for (int kc = 0; kc < kcNum; kc++) {
        __syncthreads();                 // prior B consumers done
        stageBall(kc);
        if (kc == 0) stageA(0);
        cpa_commit();
        cpa_wait0();
        __syncthreads();

        for (int tap = 0; tap < taps; tap++) {
            const int s = kc * taps + tap;
            if (s + 1 < nsteps) stageA(s + 1);
            cpa_commit();

            const int dy = tap / kw, dx = tap % kw - kr;
            const uint32_t Bt = sB + (uint32_t)((r4 + dy) * 16640);
            const uint32_t A0 = sA + (uint32_t)(s & 1) * 8192u;
#pragma unroll
            for (int ks = 0; ks < 4; ks++) {
                uint32_t bf[4][4];
#pragma unroll
                for (int np = 0; np < 4; np++) {
                    int brow = pxb + np * 16 + ((midx >> 1) << 3) + l7 + 1 + dx;
                    ldsm4(bf[np], Bt + SWZ((uint32_t)(brow * 128 + (2 * ks + (midx & 1)) * 16)));
                }
                uint32_t a[2][4];
#pragma unroll
                for (int mi = 0; mi < 2; mi++)
                    ldsm4(a[mi], A0 + SWZ((uint32_t)((cs + mi * 16 + ((midx & 1) << 3) + l7) * 128
                                                     + (2 * ks + (midx >> 1)) * 16)));
#pragma unroll
                for (int mi = 0; mi < 2; mi++)
#pragma unroll
                    for (int ni = 0; ni < 8; ni++)
                        mma16816(d[mi * 8 + ni], a[mi],
                                 bf[ni >> 1][(ni & 1) * 2], bf[ni >> 1][(ni & 1) * 2 + 1]);
            }
            cpa_wait0();
            __syncthreads();
        }
    }

    // ---- epilogue
    float bias4[2][2];
#pragma unroll
    for (int mi = 0; mi < 2; mi++)
#pragma unroll
        for (int kk = 0; kk < 2; kk++) {
            int gco = mt * 64 + cs + mi * 16 + gid + kk * 8;
            bias4[mi][kk] = (gco < coutUsed) ? bias[gco] : 0.f;
        }

    if (of32) {
        // two passes over 32-co stripes: [32co][512px + pad4] fp32 (66048 B)
        for (int p = 0; p < 2; p++) {
            if ((cs >> 5) == p) {
#pragma unroll
                for (int mi = 0; mi < 2; mi++)
#pragma unroll
                    for (int ni = 0; ni < 8; ni++)
#pragma unroll
                        for (int k = 0; k < 4; k++) {
                            int coL = mi * 16 + gid + ((k >> 1) << 3);
                            int px = r4 * 128 + pxb + ni * 8 + 2 * tig + (k & 1);
                            float v = fmaxf(d[mi * 8 + ni][k] + bias4[mi][k >> 1], 0.f);
                            *reinterpret_cast<float*>(smem + (coL * 516 + px) * 4) = v;
                        }
            }
            __syncthreads();
            for (int i = tid; i < 32 * 128; i += 512) {
                int row = i >> 7, q = i & 127;
                int gco = mt * 64 + p * 32 + row;
                if (gco < coutUsed) {
                    int px0 = q * 4;
                    int hh = h0 + (px0 >> 7), pxr = px0 & 127;
                    uint4 v = *reinterpret_cast<uint4*>(smem + (row * 516 + px0) * 4);
                    *reinterpret_cast<uint4*>(
                        of32 + (((size_t)b * 128 + gco) * Hc + hh) * Wc + pxr) = v;
                }
            }
            __syncthreads();
        }
    } else {
        // [px 512][co 64 + pad8] fp16 (73728 B)
#pragma unroll
        for (int mi = 0; mi < 2; mi++)
#pragma unroll
            for (int ni = 0; ni < 8; ni++)
#pragma unroll
                for (int k = 0; k < 4; k++) {
                    int co = cs + mi * 16 + gid + ((k >> 1) << 3);
                    int px = r4 * 128 + pxb + ni * 8 + 2 * tig + (k & 1);
                    float v = fmaxf(d[mi * 8 + ni][k] + bias4[mi][k >> 1], 0.f);
                    *reinterpret_cast<__half*>(smem + px * 144 + co * 2) = __float2half(v);
                }
        __syncthreads();
        for (int i = tid; i < 512 * 8; i += 512) {
            int row = i >> 3, q = i & 7;            // row = px (0..511)
            int hh = h0 + (row >> 7), pxr = row & 127;
            int gcoB = mt * 64 + q * 8;
            size_t dst = (((size_t)b * Hc + hh) * Wc + pxr) * outCpad + outCoff + mt * 64 + q * 8;
            uint4 vh = *reinterpret_cast<uint4*>(smem + row * 144 + q * 16);
            if (gcoB + 8 <= coutUsed) {
                *reinterpret_cast<uint4*>(oh + dst) = vh;
            } else if (gcoB < coutUsed) {
                const __half* ph = reinterpret_cast<const __half*>(&vh);
                for (int e = 0; e < coutUsed - gcoB; e++) oh[dst + e] = ph[e];
            }
        }
    }
}

// append flow into output channels 126..127 (NCHW fp32)
__global__ void concat_flow_k(const float* __restrict__ flow, float* __restrict__ out)
{
    int i = blockIdx.x * 256 + threadIdx.x;
    if (i < Bn * 2 * HW) {
        int b = i / (2 * HW);
        int r = i % (2 * HW);
        out[(size_t)b * 128 * HW + (size_t)126 * HW + r] = flow[i];
    }
}

// ---------------------------------------------------------------------------
extern "C" void kernel_launch(void* const* d_in, const int* in_sizes, int n_in,
                              void* d_out, int out_size)
{
    const float* flow = (const float*)d_in[0];
    const float* corr = (const float*)d_in[1];
    const float* wc1  = (const float*)d_in[2];
    const float* bc1  = (const float*)d_in[3];
    const float* wc2  = (const float*)d_in[4];
    const float* bc2  = (const float*)d_in[5];
    const float* wf1  = (const float*)d_in[6];
    const float* bf1  = (const float*)d_in[7];
    const float* wf2  = (const float*)d_in[8];
    const float* bf2  = (const float*)d_in[9];
    const float* wo   = (const float*)d_in[10];
    const float* bo   = (const float*)d_in[11];
    float* out = (float*)d_out;

    __half *corrh, *cor1h, *flo1h, *cath, *im7, *wc1h, *wc2h, *wf2h, *woh, *wf1h;
    cudaGetSymbolAddress((void**)&corrh, g_corr_h);
    cudaGetSymbolAddress((void**)&cor1h, g_cor1_h);
    cudaGetSymbolAddress((void**)&flo1h, g_flo1_h);
    cudaGetSymbolAddress((void**)&cath,  g_cat_h);
    cudaGetSymbolAddress((void**)&im7,   g_im7);
    cudaGetSymbolAddress((void**)&wc1h,  g_wc1_h);
    cudaGetSymbolAddress((void**)&wc2h,  g_wc2_h);
    cudaGetSymbolAddress((void**)&wf2h,  g_wf2_h);
    cudaGetSymbolAddress((void**)&woh,   g_wo_h);
    cudaGetSymbolAddress((void**)&wf1h,  g_wf1_h);

    cudaFuncSetAttribute(conv_mma4_k, cudaFuncAttributeMaxDynamicSharedMemorySize, SMEM_BYTES);

    // 0: all weight prep
    wprep_all_k<<<256, 256>>>(wc1, wc2, wf2, wo, wf1, wc1h, wc2h, wf2h, woh, wf1h);
    // 1: im2col of flow for the 7x7 conv
    im2col7_k<<<dim3(Hc, Bn), 128>>>(flow, im7);
    // 2: corr layout
    corr2nhwc_k<<<dim3(12, Hc, Bn), 256>>>(corr, corrh);
    // 3: cor1 = relu(conv1x1(corr))            M=256 -> x=4
    conv_mma4_k<<<dim3(4, Hc / 4, Bn), 512, SMEM_BYTES>>>(
        corrh, 384, 6, wc1h, 256, bc1, 256, 1, 1, 0,
        cor1h, 256, 0, nullptr);
    // 4: flo1 = relu(conv7x7(flow)) == im7 GEMM  M=128 -> x=2
    conv_mma4_k<<<dim3(2, Hc / 4, Bn), 512, SMEM_BYTES>>>(
        im7, 128, 2, wf1h, 128, bf1, 128, 1, 1, 0,
        flo1h, 128, 0, nullptr);
    // 5 (ncu target): cat[:,0:192] = relu(conv3x3(cor1))  M=192 -> x=3
    conv_mma4_k<<<dim3(3, Hc / 4, Bn), 512, SMEM_BYTES>>>(
        cor1h, 256, 4, wc2h, 256, bc2, 192, 9, 3, 1,
        cath, 256, 0, nullptr);
    // 6: cat[:,192:256] = relu(conv3x3(flo1))  M=64 -> x=1
    conv_mma4_k<<<dim3(1, Hc / 4, Bn), 512, SMEM_BYTES>>>(
        flo1h, 128, 2, wf2h, 128, bf2, 64, 9, 3, 1,
        cath, 256, 192, nullptr);
    // 7: d_out[:,0:126] = relu(conv3x3(cat))   (fp32 NCHW) M=128 -> x=2
    conv_mma4_k<<<dim3(2, Hc / 4, Bn), 512, SMEM_BYTES>>>(
        cath, 256, 4, woh, 128, bo, 126, 9, 3, 1,
        nullptr, 128, 0, out);
    // 8: d_out[:,126:128] = flow
    concat_flow_k<<<(Bn * 2 * HW + 255) / 256, 256>>>(flow, out);
}

// round 13
// speedup vs baseline: 1.0139x; 1.0139x over previous
#include <cuda_runtime.h>
#include <cuda_fp16.h>
#include <stdint.h>

#define Bn 8
#define Hc 96
#define Wc 128
#define HW (Hc*Wc)

// ---------------- scratch (__device__ globals; allocation-free rule) -------
__device__ __half g_corr_h[(size_t)Bn*HW*384];
__device__ __half g_cor1_h[(size_t)Bn*HW*256];
__device__ __half g_flo1_h[(size_t)Bn*HW*128];
__device__ __half g_cat_h [(size_t)Bn*HW*256];
__device__ __half g_im7  [(size_t)Bn*HW*128];     // im2col of flow (7x7, Cin=2)
__device__ __half g_wc1_h[1*256*384];
__device__ __half g_wc2_h[9*256*256];
__device__ __half g_wf2_h[9*128*128];
__device__ __half g_wo_h [9*128*256];
__device__ __half g_wf1_h[128*128];               // im2col-matched 7x7 weights

// ---------------- helpers ---------------------------------------------------
__device__ __forceinline__ uint32_t s2u(const void* p) {
    uint32_t a;
    asm("{ .reg .u64 t; cvta.to.shared.u64 t, %1; cvt.u32.u64 %0, t; }"
        : "=r"(a) : "l"(p));
    return a;
}
#define SWZ(x) ((x) ^ (((x) >> 3) & 0x70))

__device__ __forceinline__ void ldsm4(uint32_t* r, uint32_t addr) {
    asm volatile("ldmatrix.sync.aligned.m8n8.x4.shared.b16 {%0,%1,%2,%3}, [%4];"
        : "=r"(r[0]), "=r"(r[1]), "=r"(r[2]), "=r"(r[3]) : "r"(addr));
}
__device__ __forceinline__ void mma16816(float* d, const uint32_t* a,
                                          uint32_t b0, uint32_t b1) {
    asm volatile(
        "mma.sync.aligned.m16n8k16.row.col.f32.f16.f16.f32 "
        "{%0,%1,%2,%3}, {%4,%5,%6,%7}, {%8,%9}, {%0,%1,%2,%3};"
        : "+f"(d[0]), "+f"(d[1]), "+f"(d[2]), "+f"(d[3])
        : "r"(a[0]), "r"(a[1]), "r"(a[2]), "r"(a[3]), "r"(b0), "r"(b1));
}
__device__ __forceinline__ void cpa16(uint32_t s, const void* g, bool p) {
    asm volatile("cp.async.ca.shared.global [%0], [%1], 16, %2;"
        :: "r"(s), "l"(g), "r"(p ? 16u : 0u));
}
__device__ __forceinline__ void cpa_commit() {
    asm volatile("cp.async.commit_group;" ::: "memory");
}
__device__ __forceinline__ void cpa_wait0() {
    asm volatile("cp.async.wait_group 0;" ::: "memory");
}

// ---------------- weight prep (ALL layers, one launch) ----------------------
__device__ __forceinline__ void prep1(const float* __restrict__ w, int cout,
                                      int cin, int taps, int coPad, int Cpad,
                                      __half* __restrict__ dst, size_t i)
{
    int ci = (int)(i % Cpad);
    size_t t = i / Cpad;
    int co = (int)(t % coPad);
    int tap = (int)(t / coPad);
    float v = 0.f;
    if (co < cout && ci < cin)
        v = w[((size_t)co * cin + ci) * taps + tap];
    dst[i] = __float2half(v);
}

__global__ void wprep_all_k(const float* __restrict__ wc1, const float* __restrict__ wc2,
                            const float* __restrict__ wf2, const float* __restrict__ wo,
                            const float* __restrict__ wf1,
                            __half* __restrict__ oc1, __half* __restrict__ oc2,
                            __half* __restrict__ of2, __half* __restrict__ oo,
                            __half* __restrict__ of1)
{
    const size_t n1 = 98304, n2 = 589824, n3 = 147456, n4 = 294912, n5 = 16384;
    const size_t total = n1 + n2 + n3 + n4 + n5;
    for (size_t i = (size_t)blockIdx.x * blockDim.x + threadIdx.x; i < total;
         i += (size_t)gridDim.x * blockDim.x) {
        if (i < n1)                     prep1(wc1, 256, 324, 1, 256, 384, oc1, i);
        else if (i < n1 + n2)           prep1(wc2, 192, 256, 9, 256, 256, oc2, i - n1);
        else if (i < n1 + n2 + n3)      prep1(wf2,  64, 128, 9, 128, 128, of2, i - n1 - n2);
        else if (i < n1 + n2 + n3 + n4) prep1(wo,  126, 256, 9, 128, 256, oo,  i - n1 - n2 - n3);
        else {
            size_t i5 = i - n1 - n2 - n3 - n4;
            int co = (int)(i5 >> 7), c = (int)(i5 & 127);
            float v = 0.f;
            if (c < 98)   // c = dyx*2 + ci ; w[co][ci][dyx]
                v = wf1[(size_t)co * 98 + (c & 1) * 49 + (c >> 1)];
            of1[i5] = __float2half(v);
        }
    }
}

// ---------------- corr NCHW fp32 -> NHWC fp16 (Cpad=384, zero pad) ----------
__global__ __launch_bounds__(256) void corr2nhwc_k(
    const float* __restrict__ corr, __half* __restrict__ oh)
{
    const int c0 = blockIdx.x * 32, h = blockIdx.y, b = blockIdx.z;
    __shared__ float t[32][129];
    for (int i = threadIdx.x; i < 32 * 128; i += 256) {
        int ci = i >> 7, px = i & 127;
        float v = 0.f;
        if (c0 + ci < 324)
            v = corr[((size_t)b * 324 + c0 + ci) * HW + h * Wc + px];
        t[ci][px] = v;
    }
    __syncthreads();
    for (int i = threadIdx.x; i < 32 * 128; i += 256) {
        int px = i >> 5, ci = i & 31;
        size_t o = (((size_t)b * Hc + h) * Wc + px) * 384 + c0 + ci;
        oh[o] = __float2half(t[ci][px]);
    }
}

// ---------------- im2col for the 7x7 conv: flow NCHW -> [B,H,W,128] fp16 ----
__global__ __launch_bounds__(128) void im2col7_k(
    const float* __restrict__ flow, __half* __restrict__ dst)
{
    const int w = threadIdx.x, h = blockIdx.x, b = blockIdx.y;
    __align__(16) __half v[128];
#pragma unroll
    for (int c = 98; c < 128; c++) v[c] = __float2half(0.f);
#pragma unroll
    for (int dy = 0; dy < 7; dy++) {
        int hh = h + dy - 3;
#pragma unroll
        for (int dx = 0; dx < 7; dx++) {
            int ww = w + dx - 3;
            bool p = ((unsigned)hh < Hc) && ((unsigned)ww < Wc);
#pragma unroll
            for (int ci = 0; ci < 2; ci++) {
                float f = p ? flow[((size_t)(b * 2 + ci) * Hc + hh) * Wc + ww] : 0.f;
                v[(dy * 7 + dx) * 2 + ci] = __float2half(f);
            }
        }
    }
    __half* o = dst + (((size_t)b * Hc + h) * Wc + w) * 128;
#pragma unroll
    for (int j = 0; j < 16; j++)
        reinterpret_cast<uint4*>(o)[j] = reinterpret_cast<uint4*>(v)[j];
}

// ---------------- HMMA conv-as-GEMM, 64co x 512px, B double-buffered ---------
// Block: 256 thr / 8 warps; tile 64co x 512px (FOUR image rows h0..h0+3).
// Warp w: row r4=w>>1 (0..3), px half pxb=(w&1)*64; all warps share A (64 co).
// Per warp-ks: 4 A ldsm + 4 B ldsm -> 32 mma (ratio 4.0).
// A: 2-slot ring (8KB each), staged per step (fully overlapped).
// B: TWO slots of (4+kw-1) row-tiles; B(kc+1) staging is sliced across the
// taps of kc and committed with A(s+1) -> all staging overlapped with compute.
// smem: A 16384 @0 ; B 2*nTile*16640 @16384 (max 216064). Epilogue reuses all.
#define SMEM_BYTES 216064

__global__ __launch_bounds__(256, 1) void conv_mma5_k(
    const __half* __restrict__ ah, int Cpad, int kcNum,
    const __half* __restrict__ wgh,
    int coPad, const float* __restrict__ bias, int coutUsed,
    int taps, int kw, int kr,
    __half* __restrict__ oh, int outCpad, int outCoff,
    float* __restrict__ of32)
{
    extern __shared__ __align__(16) char smem[];
    const uint32_t sA = s2u(smem);
    const uint32_t sB = sA + 16384u;

    const int tid = threadIdx.x;
    const int warp = tid >> 5, lane = tid & 31;
    const int mt = blockIdx.x, h0 = blockIdx.y * 4, b = blockIdx.z;
    const int r4 = warp >> 1;             // image row within block (0..3)
    const int pxb = (warp & 1) * 64;      // px half
    const int gid = lane >> 2, tig = lane & 3;
    const int midx = lane >> 3, l7 = lane & 7;

    float d[32][4];
#pragma unroll
    for (int i = 0; i < 32; i++)
#pragma unroll
        for (int j = 0; j < 4; j++) d[i][j] = 0.f;

    const int nsteps = kcNum * taps;
    const int nTile = 4 + kw - 1;
    const uint32_t bStride = (uint32_t)nTile * 16640u;
    const int totB = nTile * 1040;

    // stage A (64 co x 64 ci fp16) for step s into slot s&1
    auto stageA = [&](int s) {
        const int kcs = s / taps, tp = s % taps;
        const __half* src = wgh + (size_t)kcs * 64;
        const uint32_t d0 = sA + (uint32_t)(s & 1) * 8192u;
#pragma unroll
        for (int j = 0; j < 2; j++) {
            int i = tid + j * 256;
            int row = i >> 3, c16 = i & 7;
            cpa16(d0 + SWZ((uint32_t)(row * 128 + c16 * 16)),
                  src + ((size_t)tp * coPad + mt * 64 + row) * Cpad + c16 * 8, true);
        }
    };
    // stage slice [i0,i1) of B row-tiles for chunk kc into slot `slot`
    auto stageB = [&](int kc, int slot, int i0, int i1) {
        const uint32_t base = sB + (uint32_t)slot * bStride;
        for (int i = i0 + tid; i < i1; i += 256) {
            int t = i / 1040, rem = i - t * 1040;
            int row = rem >> 3, c16 = rem & 7;
            int px = row - 1;
            int hh = h0 + t - kr;
            bool p = ((unsigned)px < Wc) && ((unsigned)hh < Hc);
            const __half* g = ah + (((size_t)b * Hc + hh) * Wc + px) * Cpad
                            + kc * 64 + c16 * 8;
            cpa16(base + t * 16640 + SWZ(row * 128 + c16 * 16), p ? g : ah, p);
        }
    };

    // prologue: B(0) + A(0), single exposed wait
    stageB(0, 0, 0, totB);
    stageA(0);
    cpa_commit();
    cpa_wait0();
    __syncthreads();

    for (int kc = 0; kc < kcNum; kc++) {
        const uint32_t Bbase = sB + (uint32_t)(kc & 1) * bStride;
        for (int tap = 0; tap < taps; tap++) {
            const int s = kc * taps + tap;
            if (s + 1 < nsteps) stageA(s + 1);
            if (kc + 1 < kcNum)        // slice of next kc's B tiles
                stageB(kc + 1, (kc + 1) & 1, tap * totB / taps,
                       (tap + 1) * totB / taps);
            cpa_commit();

            const int dy = tap / kw, dx = tap % kw - kr;
            const uint32_t Bt = Bbase + (uint32_t)((r4 + dy) * 16640);
            const uint32_t A0 = sA + (uint32_t)(s & 1) * 8192u;
#pragma unroll
            for (int ks = 0; ks < 4; ks++) {
                uint32_t bf[4][4];
#pragma unroll
                for (int np = 0; np < 4; np++) {
                    int brow = pxb + np * 16 + ((midx >> 1) << 3) + l7 + 1 + dx;
                    ldsm4(bf[np], Bt + SWZ((uint32_t)(brow * 128 + (2 * ks + (midx & 1)) * 16)));
                }
                uint32_t a[4][4];
#pragma unroll
                for (int mi = 0; mi < 4; mi++)
                    ldsm4(a[mi], A0 + SWZ((uint32_t)((mi * 16 + ((midx & 1) << 3) + l7) * 128
                                                     + (2 * ks + (midx >> 1)) * 16)));
#pragma unroll
                for (int mi = 0; mi < 4; mi++)
#pragma unroll
                    for (int ni = 0; ni < 8; ni++)
                        mma16816(d[mi * 8 + ni], a[mi],
                                 bf[ni >> 1][(ni & 1) * 2], bf[ni >> 1][(ni & 1) * 2 + 1]);
            }
            cpa_wait0();
            __syncthreads();
        }
    }

    // ---- epilogue
    float bias8[4][2];
#pragma unroll
    for (int mi = 0; mi < 4; mi++)
#pragma unroll
        for (int kk = 0; kk < 2; kk++) {
            int gco = mt * 64 + mi * 16 + gid + kk * 8;
            bias8[mi][kk] = (gco < coutUsed) ? bias[gco] : 0.f;
        }

    if (of32) {
        // two passes over 32-co halves: [32co][512px + pad4] fp32 (66048 B)
        for (int p = 0; p < 2; p++) {
#pragma unroll
            for (int mi = 0; mi < 4; mi++) {
                if ((mi >> 1) != p) continue;
#pragma unroll
                for (int ni = 0; ni < 8; ni++)
#pragma unroll
                    for (int k = 0; k < 4; k++) {
                        int coL = (mi & 1) * 16 + gid + ((k >> 1) << 3);
                        int px = r4 * 128 + pxb + ni * 8 + 2 * tig + (k & 1);
                        float v = fmaxf(d[mi * 8 + ni][k] + bias8[mi][k >> 1], 0.f);
                        *reinterpret_cast<float*>(smem + (coL * 516 + px) * 4) = v;
                    }
            }
            __syncthreads();
            for (int i = tid; i < 32 * 128; i += 256) {
                int row = i >> 7, q = i & 127;
                int gco = mt * 64 + p * 32 + row;
                if (gco < coutUsed) {
                    int px0 = q * 4;
                    int hh = h0 + (px0 >> 7), pxr = px0 & 127;
                    uint4 v = *reinterpret_cast<uint4*>(smem + (row * 516 + px0) * 4);
                    *reinterpret_cast<uint4*>(
                        of32 + (((size_t)b * 128 + gco) * Hc + hh) * Wc + pxr) = v;
                }
            }
            __syncthreads();
        }
    } else {
        // [px 512][co 64 + pad8] fp16 (73728 B)
#pragma unroll
        for (int mi = 0; mi < 4; mi++)
#pragma unroll
            for (int ni = 0; ni < 8; ni++)
#pragma unroll
                for (int k = 0; k < 4; k++) {
                    int co = mi * 16 + gid + ((k >> 1) << 3);
                    int px = r4 * 128 + pxb + ni * 8 + 2 * tig + (k & 1);
                    float v = fmaxf(d[mi * 8 + ni][k] + bias8[mi][k >> 1], 0.f);
                    *reinterpret_cast<__half*>(smem + px * 144 + co * 2) = __float2half(v);
                }
        __syncthreads();
        for (int i = tid; i < 512 * 8; i += 256) {
            int row = i >> 3, q = i & 7;            // row = px (0..511)
            int hh = h0 + (row >> 7), pxr = row & 127;
            int gcoB = mt * 64 + q * 8;
            size_t dst = (((size_t)b * Hc + hh) * Wc + pxr) * outCpad + outCoff + mt * 64 + q * 8;
            uint4 vh = *reinterpret_cast<uint4*>(smem + row * 144 + q * 16);
            if (gcoB + 8 <= coutUsed) {
                *reinterpret_cast<uint4*>(oh + dst) = vh;
            } else if (gcoB < coutUsed) {
                const __half* ph = reinterpret_cast<const __half*>(&vh);
                for (int e = 0; e < coutUsed - gcoB; e++) oh[dst + e] = ph[e];
            }
        }
    }
}

// append flow into output channels 126..127 (NCHW fp32)
__global__ void concat_flow_k(const float* __restrict__ flow, float* __restrict__ out)
{
    int i = blockIdx.x * 256 + threadIdx.x;
    if (i < Bn * 2 * HW) {
        int b = i / (2 * HW);
        int r = i % (2 * HW);
        out[(size_t)b * 128 * HW + (size_t)126 * HW + r] = flow[i];
    }
}

// ---------------------------------------------------------------------------
extern "C" void kernel_launch(void* const* d_in, const int* in_sizes, int n_in,
                              void* d_out, int out_size)
{
    const float* flow = (const float*)d_in[0];
    const float* corr = (const float*)d_in[1];
    const float* wc1  = (const float*)d_in[2];
    const float* bc1  = (const float*)d_in[3];
    const float* wc2  = (const float*)d_in[4];
    const float* bc2  = (const float*)d_in[5];
    const float* wf1  = (const float*)d_in[6];
    const float* bf1  = (const float*)d_in[7];
    const float* wf2  = (const float*)d_in[8];
    const float* bf2  = (const float*)d_in[9];
    const float* wo   = (const float*)d_in[10];
    const float* bo   = (const float*)d_in[11];
    float* out = (float*)d_out;

    __half *corrh, *cor1h, *flo1h, *cath, *im7, *wc1h, *wc2h, *wf2h, *woh, *wf1h;
    cudaGetSymbolAddress((void**)&corrh, g_corr_h);
    cudaGetSymbolAddress((void**)&cor1h, g_cor1_h);
    cudaGetSymbolAddress((void**)&flo1h, g_flo1_h);
    cudaGetSymbolAddress((void**)&cath,  g_cat_h);
    cudaGetSymbolAddress((void**)&im7,   g_im7);
    cudaGetSymbolAddress((void**)&wc1h,  g_wc1_h);
    cudaGetSymbolAddress((void**)&wc2h,  g_wc2_h);
    cudaGetSymbolAddress((void**)&wf2h,  g_wf2_h);
    cudaGetSymbolAddress((void**)&woh,   g_wo_h);
    cudaGetSymbolAddress((void**)&wf1h,  g_wf1_h);

    cudaFuncSetAttribute(conv_mma5_k, cudaFuncAttributeMaxDynamicSharedMemorySize, SMEM_BYTES);

    // 0: all weight prep
    wprep_all_k<<<256, 256>>>(wc1, wc2, wf2, wo, wf1, wc1h, wc2h, wf2h, woh, wf1h);
    // 1: im2col of flow for the 7x7 conv
    im2col7_k<<<dim3(Hc, Bn), 128>>>(flow, im7);
    // 2: corr layout
    corr2nhwc_k<<<dim3(12, Hc, Bn), 256>>>(corr, corrh);
    // 3: cor1 = relu(conv1x1(corr))            M=256 -> x=4
    conv_mma5_k<<<dim3(4, Hc / 4, Bn), 256, SMEM_BYTES>>>(
        corrh, 384, 6, wc1h, 256, bc1, 256, 1, 1, 0,
        cor1h, 256, 0, nullptr);
    // 4: flo1 = relu(conv7x7(flow)) == im7 GEMM  M=128 -> x=2
    conv_mma5_k<<<dim3(2, Hc / 4, Bn), 256, SMEM_BYTES>>>(
        im7, 128, 2, wf1h, 128, bf1, 128, 1, 1, 0,
        flo1h, 128, 0, nullptr);
    // 5 (ncu target): cat[:,0:192] = relu(conv3x3(cor1))  M=192 -> x=3
    conv_mma5_k<<<dim3(3, Hc / 4, Bn), 256, SMEM_BYTES>>>(
        cor1h, 256, 4, wc2h, 256, bc2, 192, 9, 3, 1,
        cath, 256, 0, nullptr);
    // 6: cat[:,192:256] = relu(conv3x3(flo1))  M=64 -> x=1
    conv_mma5_k<<<dim3(1, Hc / 4, Bn), 256, SMEM_BYTES>>>(
        flo1h, 128, 2, wf2h, 128, bf2, 64, 9, 3, 1,
        cath, 256, 192, nullptr);
    // 7: d_out[:,0:126] = relu(conv3x3(cat))   (fp32 NCHW) M=128 -> x=2
    conv_mma5_k<<<dim3(2, Hc / 4, Bn), 256, SMEM_BYTES>>>(
        cath, 256, 4, woh, 128, bo, 126, 9, 3, 1,
        nullptr, 128, 0, out);
    // 8: d_out[:,126:128] = flow
    concat_flow_k<<<(Bn * 2 * HW + 255) / 256, 256>>>(flow, out);
}

// round 14
// speedup vs baseline: 1.1397x; 1.1240x over previous
#include <cuda_runtime.h>
#include <cuda_fp16.h>
#include <stdint.h>

#define Bn 8
#define Hc 96
#define Wc 128
#define HW (Hc*Wc)

// ---------------- scratch (__device__ globals; allocation-free rule) -------
__device__ __half g_corr_h[(size_t)Bn*HW*384];
__device__ __half g_cor1_h[(size_t)Bn*HW*256];
__device__ __half g_flo1_h[(size_t)Bn*HW*128];
__device__ __half g_cat_h [(size_t)Bn*HW*256];
__device__ __half g_im7  [(size_t)Bn*HW*128];     // im2col of flow (7x7, Cin=2)
__device__ __half g_wc1_h[1*256*384];
__device__ __half g_wc2_h[9*256*256];
__device__ __half g_wf2_h[9*128*128];
__device__ __half g_wo_h [9*128*256];
__device__ __half g_wf1_h[128*128];               // im2col-matched 7x7 weights

// ---------------- helpers ---------------------------------------------------
__device__ __forceinline__ uint32_t s2u(const void* p) {
    uint32_t a;
    asm("{ .reg .u64 t; cvta.to.shared.u64 t, %1; cvt.u32.u64 %0, t; }"
        : "=r"(a) : "l"(p));
    return a;
}
#define SWZ(x) ((x) ^ (((x) >> 3) & 0x70))

__device__ __forceinline__ void ldsm4(uint32_t* r, uint32_t addr) {
    asm volatile("ldmatrix.sync.aligned.m8n8.x4.shared.b16 {%0,%1,%2,%3}, [%4];"
        : "=r"(r[0]), "=r"(r[1]), "=r"(r[2]), "=r"(r[3]) : "r"(addr));
}
__device__ __forceinline__ void mma16816(float* d, const uint32_t* a,
                                          uint32_t b0, uint32_t b1) {
    asm volatile(
        "mma.sync.aligned.m16n8k16.row.col.f32.f16.f16.f32 "
        "{%0,%1,%2,%3}, {%4,%5,%6,%7}, {%8,%9}, {%0,%1,%2,%3};"
        : "+f"(d[0]), "+f"(d[1]), "+f"(d[2]), "+f"(d[3])
        : "r"(a[0]), "r"(a[1]), "r"(a[2]), "r"(a[3]), "r"(b0), "r"(b1));
}
__device__ __forceinline__ void cpa16(uint32_t s, const void* g, bool p) {
    asm volatile("cp.async.ca.shared.global [%0], [%1], 16, %2;"
        :: "r"(s), "l"(g), "r"(p ? 16u : 0u));
}
__device__ __forceinline__ void cpa_commit() {
    asm volatile("cp.async.commit_group;" ::: "memory");
}
__device__ __forceinline__ void cpa_wait0() {
    asm volatile("cp.async.wait_group 0;" ::: "memory");
}

// ---------------- weight prep (ALL layers, one launch) ----------------------
__device__ __forceinline__ void prep1(const float* __restrict__ w, int cout,
                                      int cin, int taps, int coPad, int Cpad,
                                      __half* __restrict__ dst, size_t i)
{
    int ci = (int)(i % Cpad);
    size_t t = i / Cpad;
    int co = (int)(t % coPad);
    int tap = (int)(t / coPad);
    float v = 0.f;
    if (co < cout && ci < cin)
        v = w[((size_t)co * cin + ci) * taps + tap];
    dst[i] = __float2half(v);
}

__global__ void wprep_all_k(const float* __restrict__ wc1, const float* __restrict__ wc2,
                            const float* __restrict__ wf2, const float* __restrict__ wo,
                            const float* __restrict__ wf1,
                            __half* __restrict__ oc1, __half* __restrict__ oc2,
                            __half* __restrict__ of2, __half* __restrict__ oo,
                            __half* __restrict__ of1)
{
    const size_t n1 = 98304, n2 = 589824, n3 = 147456, n4 = 294912, n5 = 16384;
    const size_t total = n1 + n2 + n3 + n4 + n5;
    for (size_t i = (size_t)blockIdx.x * blockDim.x + threadIdx.x; i < total;
         i += (size_t)gridDim.x * blockDim.x) {
        if (i < n1)                     prep1(wc1, 256, 324, 1, 256, 384, oc1, i);
        else if (i < n1 + n2)           prep1(wc2, 192, 256, 9, 256, 256, oc2, i - n1);
        else if (i < n1 + n2 + n3)      prep1(wf2,  64, 128, 9, 128, 128, of2, i - n1 - n2);
        else if (i < n1 + n2 + n3 + n4) prep1(wo,  126, 256, 9, 128, 256, oo,  i - n1 - n2 - n3);
        else {
            size_t i5 = i - n1 - n2 - n3 - n4;
            int co = (int)(i5 >> 7), c = (int)(i5 & 127);
            float v = 0.f;
            if (c < 98)   // c = dyx*2 + ci ; w[co][ci][dyx]
                v = wf1[(size_t)co * 98 + (c & 1) * 49 + (c >> 1)];
            of1[i5] = __float2half(v);
        }
    }
}

// ---------------- corr NCHW fp32 -> NHWC fp16 (Cpad=384, zero pad) ----------
__global__ __launch_bounds__(256) void corr2nhwc_k(
    const float* __restrict__ corr, __half* __restrict__ oh)
{
    const int c0 = blockIdx.x * 32, h = blockIdx.y, b = blockIdx.z;
    __shared__ float t[32][129];
    for (int i = threadIdx.x; i < 32 * 128; i += 256) {
        int ci = i >> 7, px = i & 127;
        float v = 0.f;
        if (c0 + ci < 324)
            v = corr[((size_t)b * 324 + c0 + ci) * HW + h * Wc + px];
        t[ci][px] = v;
    }
    __syncthreads();
    for (int i = threadIdx.x; i < 32 * 128; i += 256) {
        int px = i >> 5, ci = i & 31;
        size_t o = (((size_t)b * Hc + h) * Wc + px) * 384 + c0 + ci;
        oh[o] = __float2half(t[ci][px]);
    }
}

// ---------------- im2col for the 7x7 conv: flow NCHW -> [B,H,W,128] fp16 ----
__global__ __launch_bounds__(128) void im2col7_k(
    const float* __restrict__ flow, __half* __restrict__ dst)
{
    const int w = threadIdx.x, h = blockIdx.x, b = blockIdx.y;
    __align__(16) __half v[128];
#pragma unroll
    for (int c = 98; c < 128; c++) v[c] = __float2half(0.f);
#pragma unroll
    for (int dy = 0; dy < 7; dy++) {
        int hh = h + dy - 3;
#pragma unroll
        for (int dx = 0; dx < 7; dx++) {
            int ww = w + dx - 3;
            bool p = ((unsigned)hh < Hc) && ((unsigned)ww < Wc);
#pragma unroll
            for (int ci = 0; ci < 2; ci++) {
                float f = p ? flow[((size_t)(b * 2 + ci) * Hc + hh) * Wc + ww] : 0.f;
                v[(dy * 7 + dx) * 2 + ci] = __float2half(f);
            }
        }
    }
    __half* o = dst + (((size_t)b * Hc + h) * Wc + w) * 128;
#pragma unroll
    for (int j = 0; j < 16; j++)
        reinterpret_cast<uint4*>(o)[j] = reinterpret_cast<uint4*>(v)[j];
}

// ---------------- HMMA conv-as-GEMM, 64co x 128px, 4 blocks/SM ---------------
// Block: 128 thr / 4 warps; tile 64co x 128px (ONE image row h).
// Warp w: co stripe cs=(w>>1)*32, px half pxb=(w&1)*64; warp tile 32x64.
// A: 2-slot ring (8KB each), staged per step (fully overlapped).
// B: 2-slot ring of [130px][64ci] tiles; dy-group G+1 prefetched at the first
//    tap of group G. One commit + wait + sync per step (R9 schedule).
// smem: A 16384 @0 ; B 2x16640 @16384 (total 49664 -> 4 blocks/SM).
#define SMEM_BYTES 49664

__global__ __launch_bounds__(128, 4) void conv_mma6_k(
    const __half* __restrict__ ah, int Cpad, int kcNum,
    const __half* __restrict__ wgh,
    int coPad, const float* __restrict__ bias, int coutUsed,
    int taps, int kw, int kr,
    __half* __restrict__ oh, int outCpad, int outCoff,
    float* __restrict__ of32)
{
    extern __shared__ __align__(16) char smem[];
    const uint32_t sA = s2u(smem);
    const uint32_t sB = sA + 16384u;

    const int tid = threadIdx.x;
    const int warp = tid >> 5, lane = tid & 31;
    const int mt = blockIdx.x, h = blockIdx.y, b = blockIdx.z;
    const int cs  = (warp >> 1) * 32;     // co stripe within 64
    const int pxb = (warp & 1) * 64;      // px half
    const int gid = lane >> 2, tig = lane & 3;
    const int midx = lane >> 3, l7 = lane & 7;

    float d[16][4];
#pragma unroll
    for (int i = 0; i < 16; i++)
#pragma unroll
        for (int j = 0; j < 4; j++) d[i][j] = 0.f;

    const int nsteps = kcNum * taps;
    const int nG = kcNum * kw;            // dy-groups (square kernels)

    // stage A (64 co x 64 ci fp16) for step s into slot s&1
    auto stageA = [&](int s) {
        const int kcs = s / taps, tp = s % taps;
        const __half* src = wgh + (size_t)kcs * 64;
        const uint32_t d0 = sA + (uint32_t)(s & 1) * 8192u;
#pragma unroll
        for (int j = 0; j < 4; j++) {
            int i = tid + j * 128;
            int row = i >> 3, c16 = i & 7;
            cpa16(d0 + SWZ((uint32_t)(row * 128 + c16 * 16)),
                  src + ((size_t)tp * coPad + mt * 64 + row) * Cpad + c16 * 8, true);
        }
    };
    // stage B tile for dy-group G into slot G&1
    auto stageB = [&](int G) {
        const int kcs = G / kw, dyRow = G % kw;
        const int hh = h + dyRow - kr;
        const uint32_t dst = sB + (uint32_t)(G & 1) * 16640u;
        for (int i = tid; i < 1040; i += 128) {
            int row = i >> 3, c16 = i & 7;
            int px = row - 1;
            bool p = ((unsigned)px < Wc) && ((unsigned)hh < Hc);
            const __half* g = ah + (((size_t)b * Hc + hh) * Wc + px) * Cpad
                            + kcs * 64 + c16 * 8;
            cpa16(dst + SWZ(row * 128 + c16 * 16), p ? g : ah, p);
        }
    };

    // prologue
    stageB(0);
    stageA(0);
    cpa_commit();
    cpa_wait0();
    __syncthreads();

    for (int s = 0; s < nsteps; s++) {
        const int kc = s / taps, tap = s % taps;
        const int dyI = tap / kw, dx = tap % kw - kr;
        const int G = kc * kw + dyI;

        if (s + 1 < nsteps) stageA(s + 1);
        if (tap % kw == 0 && G + 1 < nG) stageB(G + 1);
        cpa_commit();

        const uint32_t A0 = sA + (uint32_t)(s & 1) * 8192u;
        const uint32_t Bt = sB + (uint32_t)(G & 1) * 16640u;
#pragma unroll
        for (int ks = 0; ks < 4; ks++) {
            uint32_t bf[4][4];
#pragma unroll
            for (int np = 0; np < 4; np++) {
                int brow = pxb + np * 16 + ((midx >> 1) << 3) + l7 + 1 + dx;
                ldsm4(bf[np], Bt + SWZ((uint32_t)(brow * 128 + (2 * ks + (midx & 1)) * 16)));
            }
            uint32_t a[2][4];
#pragma unroll
            for (int mi = 0; mi < 2; mi++)
                ldsm4(a[mi], A0 + SWZ((uint32_t)((cs + mi * 16 + ((midx & 1) << 3) + l7) * 128
                                                 + (2 * ks + (midx >> 1)) * 16)));
#pragma unroll
            for (int mi = 0; mi < 2; mi++)
#pragma unroll
                for (int ni = 0; ni < 8; ni++)
                    mma16816(d[mi * 8 + ni], a[mi],
                             bf[ni >> 1][(ni & 1) * 2], bf[ni >> 1][(ni & 1) * 2 + 1]);
        }
        cpa_wait0();
        __syncthreads();
    }

    // ---- epilogue: bias+relu, transpose through smem
    float bias4[2][2];
#pragma unroll
    for (int mi = 0; mi < 2; mi++)
#pragma unroll
        for (int kk = 0; kk < 2; kk++) {
            int gco = mt * 64 + cs + mi * 16 + gid + kk * 8;
            bias4[mi][kk] = (gco < coutUsed) ? bias[gco] : 0.f;
        }

    if (of32) {
        // [64co][128px + pad4] fp32 at smem+0 (33792 B)
#pragma unroll
        for (int mi = 0; mi < 2; mi++)
#pragma unroll
            for (int ni = 0; ni < 8; ni++)
#pragma unroll
                for (int k = 0; k < 4; k++) {
                    int co = cs + mi * 16 + gid + ((k >> 1) << 3);
                    int px = pxb + ni * 8 + 2 * tig + (k & 1);
                    float v = fmaxf(d[mi * 8 + ni][k] + bias4[mi][k >> 1], 0.f);
                    *reinterpret_cast<float*>(smem + (co * 132 + px) * 4) = v;
                }
        __syncthreads();
        for (int i = tid; i < 64 * 32; i += 128) {
            int row = i >> 5, q = i & 31;
            int gco = mt * 64 + row;
            if (gco < coutUsed) {
                uint4 v = *reinterpret_cast<uint4*>(smem + (row * 132 + q * 4) * 4);
                *reinterpret_cast<uint4*>(
                    of32 + (((size_t)b * 128 + gco) * Hc + h) * Wc + q * 4) = v;
            }
        }
    } else {
        // [px 128][co 64 + pad8] fp16 at smem+0 (18432 B)
#pragma unroll
        for (int mi = 0; mi < 2; mi++)
#pragma unroll
            for (int ni = 0; ni < 8; ni++)
#pragma unroll
                for (int k = 0; k < 4; k++) {
                    int co = cs + mi * 16 + gid + ((k >> 1) << 3);
                    int px = pxb + ni * 8 + 2 * tig + (k & 1);
                    float v = fmaxf(d[mi * 8 + ni][k] + bias4[mi][k >> 1], 0.f);
                    *reinterpret_cast<__half*>(smem + px * 144 + co * 2) = __float2half(v);
                }
        __syncthreads();
        for (int i = tid; i < 128 * 8; i += 128) {
            int row = i >> 3, q = i & 7;            // row = px, q = 8-co group
            int gcoB = mt * 64 + q * 8;
            size_t dst = (((size_t)b * Hc + h) * Wc + row) * outCpad + outCoff + mt * 64 + q * 8;
            uint4 vh = *reinterpret_cast<uint4*>(smem + row * 144 + q * 16);
            if (gcoB + 8 <= coutUsed) {
                *reinterpret_cast<uint4*>(oh + dst) = vh;
            } else if (gcoB < coutUsed) {
                const __half* ph = reinterpret_cast<const __half*>(&vh);
                for (int e = 0; e < coutUsed - gcoB; e++) oh[dst + e] = ph[e];
            }
        }
    }
}

// append flow into output channels 126..127 (NCHW fp32)
__global__ void concat_flow_k(const float* __restrict__ flow, float* __restrict__ out)
{
    int i = blockIdx.x * 256 + threadIdx.x;
    if (i < Bn * 2 * HW) {
        int b = i / (2 * HW);
        int r = i % (2 * HW);
        out[(size_t)b * 128 * HW + (size_t)126 * HW + r] = flow[i];
    }
}

// ---------------------------------------------------------------------------
extern "C" void kernel_launch(void* const* d_in, const int* in_sizes, int n_in,
                              void* d_out, int out_size)
{
    const float* flow = (const float*)d_in[0];
    const float* corr = (const float*)d_in[1];
    const float* wc1  = (const float*)d_in[2];
    const float* bc1  = (const float*)d_in[3];
    const float* wc2  = (const float*)d_in[4];
    const float* bc2  = (const float*)d_in[5];
    const float* wf1  = (const float*)d_in[6];
    const float* bf1  = (const float*)d_in[7];
    const float* wf2  = (const float*)d_in[8];
    const float* bf2  = (const float*)d_in[9];
    const float* wo   = (const float*)d_in[10];
    const float* bo   = (const float*)d_in[11];
    float* out = (float*)d_out;

    __half *corrh, *cor1h, *flo1h, *cath, *im7, *wc1h, *wc2h, *wf2h, *woh, *wf1h;
    cudaGetSymbolAddress((void**)&corrh, g_corr_h);
    cudaGetSymbolAddress((void**)&cor1h, g_cor1_h);
    cudaGetSymbolAddress((void**)&flo1h, g_flo1_h);
    cudaGetSymbolAddress((void**)&cath,  g_cat_h);
    cudaGetSymbolAddress((void**)&im7,   g_im7);
    cudaGetSymbolAddress((void**)&wc1h,  g_wc1_h);
    cudaGetSymbolAddress((void**)&wc2h,  g_wc2_h);
    cudaGetSymbolAddress((void**)&wf2h,  g_wf2_h);
    cudaGetSymbolAddress((void**)&woh,   g_wo_h);
    cudaGetSymbolAddress((void**)&wf1h,  g_wf1_h);

    cudaFuncSetAttribute(conv_mma6_k, cudaFuncAttributeMaxDynamicSharedMemorySize, SMEM_BYTES);

    // 0: all weight prep
    wprep_all_k<<<256, 256>>>(wc1, wc2, wf2, wo, wf1, wc1h, wc2h, wf2h, woh, wf1h);
    // 1: im2col of flow for the 7x7 conv
    im2col7_k<<<dim3(Hc, Bn), 128>>>(flow, im7);
    // 2: corr layout
    corr2nhwc_k<<<dim3(12, Hc, Bn), 256>>>(corr, corrh);
    // 3: cor1 = relu(conv1x1(corr))            M=256 -> x=4
    conv_mma6_k<<<dim3(4, Hc, Bn), 128, SMEM_BYTES>>>(
        corrh, 384, 6, wc1h, 256, bc1, 256, 1, 1, 0,
        cor1h, 256, 0, nullptr);
    // 4: flo1 = relu(conv7x7(flow)) == im7 GEMM  M=128 -> x=2
    conv_mma6_k<<<dim3(2, Hc, Bn), 128, SMEM_BYTES>>>(
        im7, 128, 2, wf1h, 128, bf1, 128, 1, 1, 0,
        flo1h, 128, 0, nullptr);
    // 5 (ncu target): cat[:,0:192] = relu(conv3x3(cor1))  M=192 -> x=3
    conv_mma6_k<<<dim3(3, Hc, Bn), 128, SMEM_BYTES>>>(
        cor1h, 256, 4, wc2h, 256, bc2, 192, 9, 3, 1,
        cath, 256, 0, nullptr);
    // 6: cat[:,192:256] = relu(conv3x3(flo1))  M=64 -> x=1
    conv_mma6_k<<<dim3(1, Hc, Bn), 128, SMEM_BYTES>>>(
        flo1h, 128, 2, wf2h, 128, bf2, 64, 9, 3, 1,
        cath, 256, 192, nullptr);
    // 7: d_out[:,0:126] = relu(conv3x3(cat))   (fp32 NCHW) M=128 -> x=2
    conv_mma6_k<<<dim3(2, Hc, Bn), 128, SMEM_BYTES>>>(
        cath, 256, 4, woh, 128, bo, 126, 9, 3, 1,
        nullptr, 128, 0, out);
    // 8: d_out[:,126:128] = flow
    concat_flow_k<<<(Bn * 2 * HW + 255) / 256, 256>>>(flow, out);
}

// round 15
// speedup vs baseline: 1.1444x; 1.0041x over previous
#include <cuda_runtime.h>
#include <cuda_fp16.h>
#include <stdint.h>

#define Bn 8
#define Hc 96
#define Wc 128
#define HW (Hc*Wc)

// ---------------- scratch (__device__ globals; allocation-free rule) -------
__device__ __half g_corr_h[(size_t)Bn*HW*384];
__device__ __half g_cor1_h[(size_t)Bn*HW*256];
__device__ __half g_flo1_h[(size_t)Bn*HW*128];
__device__ __half g_cat_h [(size_t)Bn*HW*256];
__device__ __half g_im7  [(size_t)Bn*HW*128];     // im2col of flow (7x7, Cin=2)
__device__ __half g_wc1_h[1*256*384];
__device__ __half g_wc2_h[9*256*256];
__device__ __half g_wf2_h[9*128*128];
__device__ __half g_wo_h [9*128*256];
__device__ __half g_wf1_h[128*128];               // im2col-matched 7x7 weights

// ---------------- helpers ---------------------------------------------------
__device__ __forceinline__ uint32_t s2u(const void* p) {
    uint32_t a;
    asm("{ .reg .u64 t; cvta.to.shared.u64 t, %1; cvt.u32.u64 %0, t; }"
        : "=r"(a) : "l"(p));
    return a;
}
#define SWZ(x) ((x) ^ (((x) >> 3) & 0x70))

__device__ __forceinline__ void ldsm4(uint32_t* r, uint32_t addr) {
    asm volatile("ldmatrix.sync.aligned.m8n8.x4.shared.b16 {%0,%1,%2,%3}, [%4];"
        : "=r"(r[0]), "=r"(r[1]), "=r"(r[2]), "=r"(r[3]) : "r"(addr));
}
__device__ __forceinline__ void mma16816(float* d, const uint32_t* a,
                                          uint32_t b0, uint32_t b1) {
    asm volatile(
        "mma.sync.aligned.m16n8k16.row.col.f32.f16.f16.f32 "
        "{%0,%1,%2,%3}, {%4,%5,%6,%7}, {%8,%9}, {%0,%1,%2,%3};"
        : "+f"(d[0]), "+f"(d[1]), "+f"(d[2]), "+f"(d[3])
        : "r"(a[0]), "r"(a[1]), "r"(a[2]), "r"(a[3]), "r"(b0), "r"(b1));
}
__device__ __forceinline__ void cpa16(uint32_t s, const void* g, bool p) {
    asm volatile("cp.async.ca.shared.global [%0], [%1], 16, %2;"
        :: "r"(s), "l"(g), "r"(p ? 16u : 0u));
}
__device__ __forceinline__ void cpa_commit() {
    asm volatile("cp.async.commit_group;" ::: "memory");
}
__device__ __forceinline__ void cpa_wait0() {
    asm volatile("cp.async.wait_group 0;" ::: "memory");
}

// ---------------- weight prep + concat (ALL layers, one launch) -------------
__device__ __forceinline__ void prep1(const float* __restrict__ w, int cout,
                                      int cin, int taps, int coPad, int Cpad,
                                      __half* __restrict__ dst, size_t i)
{
    int ci = (int)(i % Cpad);
    size_t t = i / Cpad;
    int co = (int)(t % coPad);
    int tap = (int)(t / coPad);
    float v = 0.f;
    if (co < cout && ci < cin)
        v = w[((size_t)co * cin + ci) * taps + tap];
    dst[i] = __float2half(v);
}

__global__ void wprep_all_k(const float* __restrict__ wc1, const float* __restrict__ wc2,
                            const float* __restrict__ wf2, const float* __restrict__ wo,
                            const float* __restrict__ wf1, const float* __restrict__ flow,
                            __half* __restrict__ oc1, __half* __restrict__ oc2,
                            __half* __restrict__ of2, __half* __restrict__ oo,
                            __half* __restrict__ of1, float* __restrict__ outp)
{
    const size_t n1 = 98304, n2 = 589824, n3 = 147456, n4 = 294912, n5 = 16384;
    const size_t n6 = (size_t)Bn * 2 * HW;   // concat flow -> out ch 126..127
    const size_t total = n1 + n2 + n3 + n4 + n5 + n6;
    for (size_t i = (size_t)blockIdx.x * blockDim.x + threadIdx.x; i < total;
         i += (size_t)gridDim.x * blockDim.x) {
        if (i < n1)                     prep1(wc1, 256, 324, 1, 256, 384, oc1, i);
        else if (i < n1 + n2)           prep1(wc2, 192, 256, 9, 256, 256, oc2, i - n1);
        else if (i < n1 + n2 + n3)      prep1(wf2,  64, 128, 9, 128, 128, of2, i - n1 - n2);
        else if (i < n1 + n2 + n3 + n4) prep1(wo,  126, 256, 9, 128, 256, oo,  i - n1 - n2 - n3);
        else if (i < n1 + n2 + n3 + n4 + n5) {
            size_t i5 = i - n1 - n2 - n3 - n4;
            int co = (int)(i5 >> 7), c = (int)(i5 & 127);
            float v = 0.f;
            if (c < 98)   // c = dyx*2 + ci ; w[co][ci][dyx]
                v = wf1[(size_t)co * 98 + (c & 1) * 49 + (c >> 1)];
            of1[i5] = __float2half(v);
        } else {
            size_t i6 = i - n1 - n2 - n3 - n4 - n5;
            int b = (int)(i6 / (2 * HW));
            int r = (int)(i6 % (2 * HW));
            outp[(size_t)b * 128 * HW + (size_t)126 * HW + r] = flow[i6];
        }
    }
}

// ---------------- corr NCHW fp32 -> NHWC fp16 (Cpad=384, zero pad) ----------
__global__ __launch_bounds__(256) void corr2nhwc_k(
    const float* __restrict__ corr, __half* __restrict__ oh)
{
    const int c0 = blockIdx.x * 32, h = blockIdx.y, b = blockIdx.z;
    __shared__ float t[32][129];
    for (int i = threadIdx.x; i < 32 * 128; i += 256) {
        int ci = i >> 7, px = i & 127;
        float v = 0.f;
        if (c0 + ci < 324)
            v = corr[((size_t)b * 324 + c0 + ci) * HW + h * Wc + px];
        t[ci][px] = v;
    }
    __syncthreads();
    for (int i = threadIdx.x; i < 32 * 128; i += 256) {
        int px = i >> 5, ci = i & 31;
        size_t o = (((size_t)b * Hc + h) * Wc + px) * 384 + c0 + ci;
        oh[o] = __float2half(t[ci][px]);
    }
}

// ---------------- im2col for the 7x7 conv: flow NCHW -> [B,H,W,128] fp16 ----
__global__ __launch_bounds__(128) void im2col7_k(
    const float* __restrict__ flow, __half* __restrict__ dst)
{
    const int w = threadIdx.x, h = blockIdx.x, b = blockIdx.y;
    __align__(16) __half v[128];
#pragma unroll
    for (int c = 98; c < 128; c++) v[c] = __float2half(0.f);
#pragma unroll
    for (int dy = 0; dy < 7; dy++) {
        int hh = h + dy - 3;
#pragma unroll
        for (int dx = 0; dx < 7; dx++) {
            int ww = w + dx - 3;
            bool p = ((unsigned)hh < Hc) && ((unsigned)ww < Wc);
#pragma unroll
            for (int ci = 0; ci < 2; ci++) {
                float f = p ? flow[((size_t)(b * 2 + ci) * Hc + hh) * Wc + ww] : 0.f;
                v[(dy * 7 + dx) * 2 + ci] = __float2half(f);
            }
        }
    }
    __half* o = dst + (((size_t)b * Hc + h) * Wc + w) * 128;
#pragma unroll
    for (int j = 0; j < 16; j++)
        reinterpret_cast<uint4*>(o)[j] = reinterpret_cast<uint4*>(v)[j];
}

// ---------------- HMMA conv-as-GEMM, templated shape, dual-args --------------
// Block: 128 thr / 4 warps; tile 64co x 128px (ONE image row h).
// Warp w: co stripe cs=(w>>1)*32, px half pxb=(w&1)*64; warp tile 32x64.
// A: 2-slot ring (8KB); B: 2-slot ring of [130px][64ci] dy-group tiles.
// One commit + wait + sync per step. smem 49664 -> 4 blocks/SM.
#define SMEM_BYTES 49664

struct CArgs {
    const __half* ah; const __half* wgh; const float* bias;
    __half* oh; float* of32;
    int Cpad, kcNum, coPad, coutUsed, outCpad, outCoff, gx;
};

template<int TAPS, int KW, int KR>
__global__ __launch_bounds__(128, 4) void conv_tmpl_k(CArgs P0, CArgs P1)
{
    extern __shared__ __align__(16) char smem[];
    const uint32_t sA = s2u(smem);
    const uint32_t sB = sA + 16384u;

    const bool first = (int)blockIdx.x < P0.gx;
    const CArgs c = first ? P0 : P1;
    const int mt = first ? blockIdx.x : blockIdx.x - P0.gx;

    const int tid = threadIdx.x;
    const int warp = tid >> 5, lane = tid & 31;
    const int h = blockIdx.y, b = blockIdx.z;
    const int cs  = (warp >> 1) * 32;
    const int pxb = (warp & 1) * 64;
    const int gid = lane >> 2, tig = lane & 3;
    const int midx = lane >> 3, l7 = lane & 7;

    float d[16][4];
#pragma unroll
    for (int i = 0; i < 16; i++)
#pragma unroll
        for (int j = 0; j < 4; j++) d[i][j] = 0.f;

    const int nG = c.kcNum * KW;

    // stage A (64 co x 64 ci fp16) for (kcs, tp) into slot `par`
    auto stageA = [&](int kcs, int tp, int par) {
        const __half* src = c.wgh + (size_t)kcs * 64;
        const uint32_t d0 = sA + (uint32_t)par * 8192u;
#pragma unroll
        for (int j = 0; j < 4; j++) {
            int i = tid + j * 128;
            int row = i >> 3, c16 = i & 7;
            cpa16(d0 + SWZ((uint32_t)(row * 128 + c16 * 16)),
                  src + ((size_t)tp * c.coPad + mt * 64 + row) * c.Cpad + c16 * 8, true);
        }
    };
    // stage B tile for dy-group G into slot G&1
    auto stageB = [&](int G) {
        const int kcs = G / KW, dyRow = G % KW;
        const int hh = h + dyRow - KR;
        const uint32_t dst = sB + (uint32_t)(G & 1) * 16640u;
        for (int i = tid; i < 1040; i += 128) {
            int row = i >> 3, c16 = i & 7;
            int px = row - 1;
            bool p = ((unsigned)px < Wc) && ((unsigned)hh < Hc);
            const __half* g = c.ah + (((size_t)b * Hc + hh) * Wc + px) * c.Cpad
                            + kcs * 64 + c16 * 8;
            cpa16(dst + SWZ(row * 128 + c16 * 16), p ? g : c.ah, p);
        }
    };

    // prologue
    stageB(0);
    stageA(0, 0, 0);
    cpa_commit();
    cpa_wait0();
    __syncthreads();

    int s = 0;
    for (int kc = 0; kc < c.kcNum; kc++) {
#pragma unroll
        for (int tap = 0; tap < TAPS; tap++, s++) {
            constexpr_helper:;
            const int dyI = tap / KW;                 // compile-time per unroll
            const int dx  = tap % KW - KR;            // compile-time per unroll
            const int G = kc * KW + dyI;

            // prefetch next step
            {
                const bool more = (tap + 1 < TAPS) || (kc + 1 < c.kcNum);
                if (more) {
                    const int ntap = (tap + 1 < TAPS) ? tap + 1 : 0;
                    const int nkc  = (tap + 1 < TAPS) ? kc : kc + 1;
                    stageA(nkc, ntap, (s + 1) & 1);
                }
                if (tap % KW == 0 && G + 1 < nG) stageB(G + 1);
                cpa_commit();
            }

            const uint32_t A0 = sA + (uint32_t)(s & 1) * 8192u;
            const uint32_t Bt = sB + (uint32_t)(G & 1) * 16640u;
#pragma unroll
            for (int ks = 0; ks < 4; ks++) {
                uint32_t bf[4][4];
#pragma unroll
                for (int np = 0; np < 4; np++) {
                    int brow = pxb + np * 16 + ((midx >> 1) << 3) + l7 + 1 + dx;
                    ldsm4(bf[np], Bt + SWZ((uint32_t)(brow * 128 + (2 * ks + (midx & 1)) * 16)));
                }
                uint32_t a[2][4];
#pragma unroll
                for (int mi = 0; mi < 2; mi++)
                    ldsm4(a[mi], A0 + SWZ((uint32_t)((cs + mi * 16 + ((midx & 1) << 3) + l7) * 128
                                                     + (2 * ks + (midx >> 1)) * 16)));
#pragma unroll
                for (int mi = 0; mi < 2; mi++)
#pragma unroll
                    for (int ni = 0; ni < 8; ni++)
                        mma16816(d[mi * 8 + ni], a[mi],
                                 bf[ni >> 1][(ni & 1) * 2], bf[ni >> 1][(ni & 1) * 2 + 1]);
            }
            cpa_wait0();
            __syncthreads();
        }
    }

    // ---- epilogue: bias+relu, transpose through smem
    float bias4[2][2];
#pragma unroll
    for (int mi = 0; mi < 2; mi++)
#pragma unroll
        for (int kk = 0; kk < 2; kk++) {
            int gco = mt * 64 + cs + mi * 16 + gid + kk * 8;
            bias4[mi][kk] = (gco < c.coutUsed) ? c.bias[gco] : 0.f;
        }

    if (c.of32) {
        // [64co][128px + pad4] fp32 at smem+0 (33792 B)
#pragma unroll
        for (int mi = 0; mi < 2; mi++)
#pragma unroll
            for (int ni = 0; ni < 8; ni++)
#pragma unroll
                for (int k = 0; k < 4; k++) {
                    int co = cs + mi * 16 + gid + ((k >> 1) << 3);
                    int px = pxb + ni * 8 + 2 * tig + (k & 1);
                    float v = fmaxf(d[mi * 8 + ni][k] + bias4[mi][k >> 1], 0.f);
                    *reinterpret_cast<float*>(smem + (co * 132 + px) * 4) = v;
                }
        __syncthreads();
        for (int i = tid; i < 64 * 32; i += 128) {
            int row = i >> 5, q = i & 31;
            int gco = mt * 64 + row;
            if (gco < c.coutUsed) {
                uint4 v = *reinterpret_cast<uint4*>(smem + (row * 132 + q * 4) * 4);
                *reinterpret_cast<uint4*>(
                    c.of32 + (((size_t)b * 128 + gco) * Hc + h) * Wc + q * 4) = v;
            }
        }
    } else {
        // [px 128][co 64 + pad8] fp16 at smem+0 (18432 B)
#pragma unroll
        for (int mi = 0; mi < 2; mi++)
#pragma unroll
            for (int ni = 0; ni < 8; ni++)
#pragma unroll
                for (int k = 0; k < 4; k++) {
                    int co = cs + mi * 16 + gid + ((k >> 1) << 3);
                    int px = pxb + ni * 8 + 2 * tig + (k & 1);
                    float v = fmaxf(d[mi * 8 + ni][k] + bias4[mi][k >> 1], 0.f);
                    *reinterpret_cast<__half*>(smem + px * 144 + co * 2) = __float2half(v);
                }
        __syncthreads();
        for (int i = tid; i < 128 * 8; i += 128) {
            int row = i >> 3, q = i & 7;
            int gcoB = mt * 64 + q * 8;
            size_t dst = (((size_t)b * Hc + h) * Wc + row) * c.outCpad + c.outCoff + mt * 64 + q * 8;
            uint4 vh = *reinterpret_cast<uint4*>(smem + row * 144 + q * 16);
            if (gcoB + 8 <= c.coutUsed) {
                *reinterpret_cast<uint4*>(c.oh + dst) = vh;
            } else if (gcoB < c.coutUsed) {
                const __half* ph = reinterpret_cast<const __half*>(&vh);
                for (int e = 0; e < c.coutUsed - gcoB; e++) c.oh[dst + e] = ph[e];
            }
        }
    }
}

// ---------------------------------------------------------------------------
extern "C" void kernel_launch(void* const* d_in, const int* in_sizes, int n_in,
                              void* d_out, int out_size)
{
    const float* flow = (const float*)d_in[0];
    const float* corr = (const float*)d_in[1];
    const float* wc1  = (const float*)d_in[2];
    const float* bc1  = (const float*)d_in[3];
    const float* wc2  = (const float*)d_in[4];
    const float* bc2  = (const float*)d_in[5];
    const float* wf1  = (const float*)d_in[6];
    const float* bf1  = (const float*)d_in[7];
    const float* wf2  = (const float*)d_in[8];
    const float* bf2  = (const float*)d_in[9];
    const float* wo   = (const float*)d_in[10];
    const float* bo   = (const float*)d_in[11];
    float* out = (float*)d_out;

    __half *corrh, *cor1h, *flo1h, *cath, *im7, *wc1h, *wc2h, *wf2h, *woh, *wf1h;
    cudaGetSymbolAddress((void**)&corrh, g_corr_h);
    cudaGetSymbolAddress((void**)&cor1h, g_cor1_h);
    cudaGetSymbolAddress((void**)&flo1h, g_flo1_h);
    cudaGetSymbolAddress((void**)&cath,  g_cat_h);
    cudaGetSymbolAddress((void**)&im7,   g_im7);
    cudaGetSymbolAddress((void**)&wc1h,  g_wc1_h);
    cudaGetSymbolAddress((void**)&wc2h,  g_wc2_h);
    cudaGetSymbolAddress((void**)&wf2h,  g_wf2_h);
    cudaGetSymbolAddress((void**)&woh,   g_wo_h);
    cudaGetSymbolAddress((void**)&wf1h,  g_wf1_h);

    cudaFuncSetAttribute(conv_tmpl_k<1,1,0>, cudaFuncAttributeMaxDynamicSharedMemorySize, SMEM_BYTES);
    cudaFuncSetAttribute(conv_tmpl_k<9,3,1>, cudaFuncAttributeMaxDynamicSharedMemorySize, SMEM_BYTES);

    // 0: weight prep + flow concat into out ch 126..127
    wprep_all_k<<<256, 256>>>(wc1, wc2, wf2, wo, wf1, flow,
                              wc1h, wc2h, wf2h, woh, wf1h, out);
    // 1: corr layout
    corr2nhwc_k<<<dim3(12, Hc, Bn), 256>>>(corr, corrh);
    // 2: im2col of flow for the 7x7 conv
    im2col7_k<<<dim3(Hc, Bn), 128>>>(flow, im7);

    // 3: fused {conv1x1 (x=4)} + {7x7-as-GEMM (x=2)}
    CArgs a1 = { corrh, wc1h, bc1, cor1h, nullptr, 384, 6, 256, 256, 256, 0, 4 };
    CArgs a2 = { im7,   wf1h, bf1, flo1h, nullptr, 128, 2, 128, 128, 128, 0, 2 };
    conv_tmpl_k<1,1,0><<<dim3(6, Hc, Bn), 128, SMEM_BYTES>>>(a1, a2);

    // 4: fused {cat[:,0:192]=conv3x3(cor1) (x=3)} + {cat[:,192:256]=conv3x3(flo1) (x=1)}
    CArgs b1 = { cor1h, wc2h, bc2, cath, nullptr, 256, 4, 256, 192, 256, 0, 3 };
    CArgs b2 = { flo1h, wf2h, bf2, cath, nullptr, 128, 2, 128,  64, 256, 192, 1 };
    conv_tmpl_k<9,3,1><<<dim3(4, Hc, Bn), 128, SMEM_BYTES>>>(b1, b2);

    // 5: d_out[:,0:126] = relu(conv3x3(cat))  (fp32 NCHW), x=2
    CArgs w1 = { cath, woh, bo, nullptr, out, 256, 4, 128, 126, 128, 0, 2 };
    conv_tmpl_k<9,3,1><<<dim3(2, Hc, Bn), 128, SMEM_BYTES>>>(w1, w1);
}

// round 17
// speedup vs baseline: 1.3467x; 1.1768x over previous
#include <cuda_runtime.h>
#include <cuda_fp16.h>
#include <stdint.h>

#define Bn 8
#define Hc 96
#define Wc 128
#define HW (Hc*Wc)

// ---------------- scratch (__device__ globals; allocation-free rule) -------
__device__ __half g_corr_h[(size_t)Bn*HW*384];
__device__ __half g_cor1_h[(size_t)Bn*HW*256];
__device__ __half g_flo1_h[(size_t)Bn*HW*128];
__device__ __half g_cat_h [(size_t)Bn*HW*256];
__device__ __half g_im7  [(size_t)Bn*HW*128];
__device__ __half g_wc1_h[1*256*384];
__device__ __half g_wc2_h[9*256*256];
__device__ __half g_wf2_h[9*128*128];
__device__ __half g_wo_h [9*128*256];
__device__ __half g_wf1_h[128*128];

// ---------------- helpers ---------------------------------------------------
__device__ __forceinline__ uint32_t s2u(const void* p) {
    uint32_t a;
    asm("{ .reg .u64 t; cvta.to.shared.u64 t, %1; cvt.u32.u64 %0, t; }"
        : "=r"(a) : "l"(p));
    return a;
}
#define SWZ(x) ((x) ^ (((x) >> 3) & 0x70))

__device__ __forceinline__ void ldsm4(uint32_t* r, uint32_t addr) {
    asm volatile("ldmatrix.sync.aligned.m8n8.x4.shared.b16 {%0,%1,%2,%3}, [%4];"
        : "=r"(r[0]), "=r"(r[1]), "=r"(r[2]), "=r"(r[3]) : "r"(addr));
}
__device__ __forceinline__ void mma16816(float* d, const uint32_t* a,
                                          uint32_t b0, uint32_t b1) {
    asm volatile(
        "mma.sync.aligned.m16n8k16.row.col.f32.f16.f16.f32 "
        "{%0,%1,%2,%3}, {%4,%5,%6,%7}, {%8,%9}, {%0,%1,%2,%3};"
        : "+f"(d[0]), "+f"(d[1]), "+f"(d[2]), "+f"(d[3])
        : "r"(a[0]), "r"(a[1]), "r"(a[2]), "r"(a[3]), "r"(b0), "r"(b1));
}
__device__ __forceinline__ void cpa16(uint32_t s, const void* g, bool p) {
    asm volatile("cp.async.ca.shared.global [%0], [%1], 16, %2;"
        :: "r"(s), "l"(g), "r"(p ? 16u : 0u));
}
__device__ __forceinline__ void cpa_commit() {
    asm volatile("cp.async.commit_group;" ::: "memory");
}
__device__ __forceinline__ void cpa_wait0() {
    asm volatile("cp.async.wait_group 0;" ::: "memory");
}

// ---------------- weight prep + concat (ALL layers, one launch) -------------
__device__ __forceinline__ void prep1(const float* __restrict__ w, int cout,
                                      int cin, int taps, int coPad, int Cpad,
                                      __half* __restrict__ dst, size_t i)
{
    int ci = (int)(i % Cpad);
    size_t t = i / Cpad;
    int co = (int)(t % coPad);
    int tap = (int)(t / coPad);
    float v = 0.f;
    if (co < cout && ci < cin)
        v = w[((size_t)co * cin + ci) * taps + tap];
    dst[i] = __float2half(v);
}

__global__ void wprep_all_k(const float* __restrict__ wc1, const float* __restrict__ wc2,
                            const float* __restrict__ wf2, const float* __restrict__ wo,
                            const float* __restrict__ wf1, const float* __restrict__ flow,
                            __half* __restrict__ oc1, __half* __restrict__ oc2,
                            __half* __restrict__ of2, __half* __restrict__ oo,
                            __half* __restrict__ of1, float* __restrict__ outp)
{
    const size_t n1 = 98304, n2 = 589824, n3 = 147456, n4 = 294912, n5 = 16384;
    const size_t n6 = (size_t)Bn * 2 * HW;
    const size_t total = n1 + n2 + n3 + n4 + n5 + n6;
    for (size_t i = (size_t)blockIdx.x * blockDim.x + threadIdx.x; i < total;
         i += (size_t)gridDim.x * blockDim.x) {
        if (i < n1)                     prep1(wc1, 256, 324, 1, 256, 384, oc1, i);
        else if (i < n1 + n2)           prep1(wc2, 192, 256, 9, 256, 256, oc2, i - n1);
        else if (i < n1 + n2 + n3)      prep1(wf2,  64, 128, 9, 128, 128, of2, i - n1 - n2);
        else if (i < n1 + n2 + n3 + n4) prep1(wo,  126, 256, 9, 128, 256, oo,  i - n1 - n2 - n3);
        else if (i < n1 + n2 + n3 + n4 + n5) {
            size_t i5 = i - n1 - n2 - n3 - n4;
            int co = (int)(i5 >> 7), c = (int)(i5 & 127);
            float v = 0.f;
            if (c < 98)
                v = wf1[(size_t)co * 98 + (c & 1) * 49 + (c >> 1)];
            of1[i5] = __float2half(v);
        } else {
            size_t i6 = i - n1 - n2 - n3 - n4 - n5;
            int b = (int)(i6 / (2 * HW));
            int r = (int)(i6 % (2 * HW));
            outp[(size_t)b * 128 * HW + (size_t)126 * HW + r] = flow[i6];
        }
    }
}

// ---------------- corr NCHW fp32 -> NHWC fp16 (Cpad=384, zero pad) ----------
__global__ __launch_bounds__(256) void corr2nhwc_k(
    const float* __restrict__ corr, __half* __restrict__ oh)
{
    const int c0 = blockIdx.x * 32, h = blockIdx.y, b = blockIdx.z;
    __shared__ float t[32][129];
    for (int i = threadIdx.x; i < 32 * 128; i += 256) {
        int ci = i >> 7, px = i & 127;
        float v = 0.f;
        if (c0 + ci < 324)
            v = corr[((size_t)b * 324 + c0 + ci) * HW + h * Wc + px];
        t[ci][px] = v;
    }
    __syncthreads();
    for (int i = threadIdx.x; i < 32 * 128; i += 256) {
        int px = i >> 5, ci = i & 31;
        size_t o = (((size_t)b * Hc + h) * Wc + px) * 384 + c0 + ci;
        oh[o] = __float2half(t[ci][px]);
    }
}

// ---------------- im2col for the 7x7 conv: flow NCHW -> [B,H,W,128] fp16 ----
__global__ __launch_bounds__(128) void im2col7_k(
    const float* __restrict__ flow, __half* __restrict__ dst)
{
    const int w = threadIdx.x, h = blockIdx.x, b = blockIdx.y;
    __align__(16) __half v[128];
#pragma unroll
    for (int c = 98; c < 128; c++) v[c] = __float2half(0.f);
#pragma unroll
    for (int dy = 0; dy < 7; dy++) {
        int hh = h + dy - 3;
#pragma unroll
        for (int dx = 0; dx < 7; dx++) {
            int ww = w + dx - 3;
            bool p = ((unsigned)hh < Hc) && ((unsigned)ww < Wc);
#pragma unroll
            for (int ci = 0; ci < 2; ci++) {
                float f = p ? flow[((size_t)(b * 2 + ci) * Hc + hh) * Wc + ww] : 0.f;
                v[(dy * 7 + dx) * 2 + ci] = __float2half(f);
            }
        }
    }
    __half* o = dst + (((size_t)b * Hc + h) * Wc + w) * 128;
#pragma unroll
    for (int j = 0; j < 16; j++)
        reinterpret_cast<uint4*>(o)[j] = reinterpret_cast<uint4*>(v)[j];
}

// ---------------- HMMA conv-as-GEMM, strength-reduced addressing ------------
// Block: 128 thr / 4 warps; tile 64co x 128px (one image row h); 4 blocks/SM.
#define SMEM_BYTES 49664

struct CArgs {
    const __half* ah; const __half* wgh; const float* bias;
    __half* oh; float* of32;
    int Cpad, kcNum, coPad, coutUsed, outCpad, outCoff, gx;
};

template<int TAPS, int KW, int KR>
__global__ __launch_bounds__(128, 4) void conv_tmpl_k(CArgs P0, CArgs P1)
{
    extern __shared__ __align__(16) char smem[];
    const uint32_t sA = s2u(smem);
    const uint32_t sB = sA + 16384u;

    const bool first = (int)blockIdx.x < P0.gx;
    const CArgs c = first ? P0 : P1;
    const int mt = first ? blockIdx.x : blockIdx.x - P0.gx;

    const int tid = threadIdx.x;
    const int warp = tid >> 5, lane = tid & 31;
    const int h = blockIdx.y, b = blockIdx.z;
    const int cs  = (warp >> 1) * 32;
    const int pxb = (warp & 1) * 64;
    const int gid = lane >> 2, tig = lane & 3;
    const int midx = lane >> 3, l7 = lane & 7;

    float d[16][4];
#pragma unroll
    for (int i = 0; i < 16; i++)
#pragma unroll
        for (int j = 0; j < 4; j++) d[i][j] = 0.f;

    // ---- per-thread staging constants
    const int r0 = tid >> 3, c16 = tid & 7;
    const uint32_t stDst0 = (uint32_t)(r0 * 128 + ((c16 * 16) ^ ((r0 * 16) & 0x70)));
    const bool px0ok = (r0 != 0);
    const int j16 = 16 * c.Cpad;

    // ---- per-thread ldsm constants
    const int rowA0 = cs + ((midx & 1) << 3) + l7;
    const int rowA1 = rowA0 + 16;
    const uint32_t aR0 = (uint32_t)(rowA0 * 128), aX0 = (uint32_t)((rowA0 * 16) & 0x70);
    const uint32_t aR1 = (uint32_t)(rowA1 * 128), aX1 = (uint32_t)((rowA1 * 16) & 0x70);
    const uint32_t kqA16 = (uint32_t)((midx >> 1) * 16);
    const uint32_t kqB16 = (uint32_t)((midx & 1) * 16);
    const int bR0 = pxb + ((midx >> 1) << 3) + l7 + 1;

    // ---- running global pointers
    const __half* aPtr = c.wgh + ((size_t)(mt * 64 + r0)) * c.Cpad + c16 * 8;
    const int tapStrideA = c.coPad * c.Cpad;
    const __half* bPtr = c.ah + (((size_t)b * Hc + (h - KR)) * Wc + (r0 - 1)) * c.Cpad + c16 * 8;
    const int rowStrideB = Wc * c.Cpad;
    int dyNext = 0;

    const int nG = c.kcNum * KW;
    const int nsteps = c.kcNum * TAPS;

    auto stageA = [&](int par) {
        const uint32_t d0 = sA + (uint32_t)par * 8192u + stDst0;
        const __half* p = aPtr;
#pragma unroll
        for (int j = 0; j < 4; j++) {
            cpa16(d0 + j * 2048, p, true);
            p += j16;
        }
    };
    auto stageB = [&](int slot, bool okH) {
        const uint32_t tB = sB + (uint32_t)slot * 16640u + stDst0;
        const __half* p = bPtr;
        cpa16(tB, p, okH && px0ok);
        p += j16;
#pragma unroll
        for (int j = 1; j < 8; j++) {
            cpa16(tB + j * 2048, p, okH);
            p += j16;
        }
        if (tid < 8)
            cpa16(sB + (uint32_t)slot * 16640u + 16384u + (uint32_t)(c16 * 16),
                  bPtr + (size_t)128 * c.Cpad, okH);
    };

    // prologue: zero halo row 129 of both B slots, stage group 0 + step 0
    if (tid < 16) {
        uint32_t z = sB + (uint32_t)(tid >> 3) * 16640u + SWZ(129 * 128 + (tid & 7) * 16);
        *reinterpret_cast<uint4*>((char*)smem + (z - sA)) = make_uint4(0, 0, 0, 0);
    }
    {
        bool okH0 = ((unsigned)(h - KR) < Hc);
        stageB(0, okH0);
        // advance bPtr to group 1 (FIX: wrap delta is 64 - (KW-1)*rowStrideB)
        dyNext = 1;
        if (dyNext == KW) { dyNext = 0; bPtr += 64 - (KW - 1) * rowStrideB; }
        else bPtr += rowStrideB;
        stageA(0);
        if (TAPS > 1) aPtr += tapStrideA;
        else aPtr += 64;
    }
    int tapNext = (TAPS > 1) ? 1 : 0;
    cpa_commit();
    cpa_wait0();
    __syncthreads();

    for (int kc = 0; kc < c.kcNum; kc++) {
#pragma unroll
        for (int tap = 0; tap < TAPS; tap++) {
            const int s = kc * TAPS + tap;
            const int dyI = tap / KW;
            const int dx  = tap % KW - KR;
            const int G = kc * KW + dyI;

            if (s + 1 < nsteps) {
                stageA((s + 1) & 1);
                if (tapNext + 1 < TAPS) { tapNext++; aPtr += tapStrideA; }
                else { tapNext = 0; aPtr += 64 - (TAPS - 1) * tapStrideA; }
            }
            if (tap % KW == 0 && G + 1 < nG) {
                bool okH = ((unsigned)(h + dyNext - KR) < Hc);
                stageB((G + 1) & 1, okH);
                if (dyNext + 1 == KW) { dyNext = 0; bPtr += 64 - (KW - 1) * rowStrideB; }
                else { dyNext++; bPtr += rowStrideB; }
            }
            cpa_commit();

            const uint32_t A0 = sA + (uint32_t)(s & 1) * 8192u;
            const uint32_t Bt = sB + (uint32_t)(G & 1) * 16640u;
            const uint32_t bX = (uint32_t)(((bR0 + dx) * 16) & 0x70);
            const uint32_t bRowBase = Bt + (uint32_t)((bR0 + dx) * 128);
#pragma unroll
            for (int ks = 0; ks < 4; ks++) {
                const uint32_t colBx = ((uint32_t)(ks * 32) + kqB16) ^ bX;
                uint32_t bf[4][4];
#pragma unroll
                for (int np = 0; np < 4; np++)
                    ldsm4(bf[np], bRowBase + np * 2048 + colBx);
                const uint32_t colA = (uint32_t)(ks * 32) + kqA16;
                uint32_t a[2][4];
                ldsm4(a[0], A0 + aR0 + (colA ^ aX0));
                ldsm4(a[1], A0 + aR1 + (colA ^ aX1));
#pragma unroll
                for (int mi = 0; mi < 2; mi++)
#pragma unroll
                    for (int ni = 0; ni < 8; ni++)
                        mma16816(d[mi * 8 + ni], a[mi],
                                 bf[ni >> 1][(ni & 1) * 2], bf[ni >> 1][(ni & 1) * 2 + 1]);
            }
            cpa_wait0();
            __syncthreads();
        }
    }

    // ---- epilogue: bias+relu, transpose through smem
    float bias4[2][2];
#pragma unroll
    for (int mi = 0; mi < 2; mi++)
#pragma unroll
        for (int kk = 0; kk < 2; kk++) {
            int gco = mt * 64 + cs + mi * 16 + gid + kk * 8;
            bias4[mi][kk] = (gco < c.coutUsed) ? c.bias[gco] : 0.f;
        }

    if (c.of32) {
#pragma unroll
        for (int mi = 0; mi < 2; mi++)
#pragma unroll
            for (int ni = 0; ni < 8; ni++)
#pragma unroll
                for (int k = 0; k < 4; k++) {
                    int co = cs + mi * 16 + gid + ((k >> 1) << 3);
                    int px = pxb + ni * 8 + 2 * tig + (k & 1);
                    float v = fmaxf(d[mi * 8 + ni][k] + bias4[mi][k >> 1], 0.f);
                    *reinterpret_cast<float*>(smem + (co * 132 + px) * 4) = v;
                }
        __syncthreads();
        for (int i = tid; i < 64 * 32; i += 128) {
            int row = i >> 5, q = i & 31;
            int gco = mt * 64 + row;
            if (gco < c.coutUsed) {
                uint4 v = *reinterpret_cast<uint4*>(smem + (row * 132 + q * 4) * 4);
                *reinterpret_cast<uint4*>(
                    c.of32 + (((size_t)b * 128 + gco) * Hc + h) * Wc + q * 4) = v;
            }
        }
    } else {
#pragma unroll
        for (int mi = 0; mi < 2; mi++)
#pragma unroll
            for (int ni = 0; ni < 8; ni++)
#pragma unroll
                for (int k = 0; k < 4; k++) {
                    int co = cs + mi * 16 + gid + ((k >> 1) << 3);
                    int px = pxb + ni * 8 + 2 * tig + (k & 1);
                    float v = fmaxf(d[mi * 8 + ni][k] + bias4[mi][k >> 1], 0.f);
                    *reinterpret_cast<__half*>(smem + px * 144 + co * 2) = __float2half(v);
                }
        __syncthreads();
        for (int i = tid; i < 128 * 8; i += 128) {
            int row = i >> 3, q = i & 7;
            int gcoB = mt * 64 + q * 8;
            size_t dst = (((size_t)b * Hc + h) * Wc + row) * c.outCpad + c.outCoff + mt * 64 + q * 8;
            uint4 vh = *reinterpret_cast<uint4*>(smem + row * 144 + q * 16);
            if (gcoB + 8 <= c.coutUsed) {
                *reinterpret_cast<uint4*>(c.oh + dst) = vh;
            } else if (gcoB < c.coutUsed) {
                const __half* ph = reinterpret_cast<const __half*>(&vh);
                for (int e = 0; e < c.coutUsed - gcoB; e++) c.oh[dst + e] = ph[e];
            }
        }
    }
}

// ---------------------------------------------------------------------------
extern "C" void kernel_launch(void* const* d_in, const int* in_sizes, int n_in,
                              void* d_out, int out_size)
{
    const float* flow = (const float*)d_in[0];
    const float* corr = (const float*)d_in[1];
    const float* wc1  = (const float*)d_in[2];
    const float* bc1  = (const float*)d_in[3];
    const float* wc2  = (const float*)d_in[4];
    const float* bc2  = (const float*)d_in[5];
    const float* wf1  = (const float*)d_in[6];
    const float* bf1  = (const float*)d_in[7];
    const float* wf2  = (const float*)d_in[8];
    const float* bf2  = (const float*)d_in[9];
    const float* wo   = (const float*)d_in[10];
    const float* bo   = (const float*)d_in[11];
    float* out = (float*)d_out;

    __half *corrh, *cor1h, *flo1h, *cath, *im7, *wc1h, *wc2h, *wf2h, *woh, *wf1h;
    cudaGetSymbolAddress((void**)&corrh, g_corr_h);
    cudaGetSymbolAddress((void**)&cor1h, g_cor1_h);
    cudaGetSymbolAddress((void**)&flo1h, g_flo1_h);
    cudaGetSymbolAddress((void**)&cath,  g_cat_h);
    cudaGetSymbolAddress((void**)&im7,   g_im7);
    cudaGetSymbolAddress((void**)&wc1h,  g_wc1_h);
    cudaGetSymbolAddress((void**)&wc2h,  g_wc2_h);
    cudaGetSymbolAddress((void**)&wf2h,  g_wf2_h);
    cudaGetSymbolAddress((void**)&woh,   g_wo_h);
    cudaGetSymbolAddress((void**)&wf1h,  g_wf1_h);

    cudaFuncSetAttribute(conv_tmpl_k<1,1,0>, cudaFuncAttributeMaxDynamicSharedMemorySize, SMEM_BYTES);
    cudaFuncSetAttribute(conv_tmpl_k<9,3,1>, cudaFuncAttributeMaxDynamicSharedMemorySize, SMEM_BYTES);

    // 0: weight prep + flow concat into out ch 126..127
    wprep_all_k<<<256, 256>>>(wc1, wc2, wf2, wo, wf1, flow,
                              wc1h, wc2h, wf2h, woh, wf1h, out);
    // 1: corr layout
    corr2nhwc_k<<<dim3(12, Hc, Bn), 256>>>(corr, corrh);
    // 2: im2col of flow for the 7x7 conv
    im2col7_k<<<dim3(Hc, Bn), 128>>>(flow, im7);

    // 3: fused {conv1x1 (x=4)} + {7x7-as-GEMM (x=2)}
    CArgs a1 = { corrh, wc1h, bc1, cor1h, nullptr, 384, 6, 256, 256, 256, 0, 4 };
    CArgs a2 = { im7,   wf1h, bf1, flo1h, nullptr, 128, 2, 128, 128, 128, 0, 2 };
    conv_tmpl_k<1,1,0><<<dim3(6, Hc, Bn), 128, SMEM_BYTES>>>(a1, a2);

    // 4: fused {cat[:,0:192]=conv3x3(cor1) (x=3)} + {cat[:,192:256]=conv3x3(flo1) (x=1)}
    CArgs b1 = { cor1h, wc2h, bc2, cath, nullptr, 256, 4, 256, 192, 256, 0, 3 };
    CArgs b2 = { flo1h, wf2h, bf2, cath, nullptr, 128, 2, 128,  64, 256, 192, 1 };
    conv_tmpl_k<9,3,1><<<dim3(4, Hc, Bn), 128, SMEM_BYTES>>>(b1, b2);

    // 5: d_out[:,0:126] = relu(conv3x3(cat))  (fp32 NCHW), x=2
    CArgs w1 = { cath, woh, bo, nullptr, out, 256, 4, 128, 126, 128, 0, 2 };
    conv_tmpl_k<9,3,1><<<dim3(2, Hc, Bn), 128, SMEM_BYTES>>>(w1, w1);
}